// round 1
// baseline (speedup 1.0000x reference)
#include <cuda_runtime.h>
#include <cstdint>

// DiscreteAutoregressiveFlow: exact one-hot algebra over Z_257.
// V=257 (prime), B=64, L=1024.
//
// Per reference step (forward values only):
//   state p in {0..256} U {ZERO};  logits = W[p,:] + b (or b for ZERO)
//   l = argmax(logits[0:257]); s = argmax(logits[257:514])
//   if s==0: out = zeros, next state = ZERO
//   else:    out = one-hot( ((x_t - l) * inv(s)) mod 257 ), next state = out index
//
// Rewritten: next = (x_t * m[p] + c[p]) mod 257, m[p]=inv(s_p), c[p]=(-l_p*m_p) mod 257.
// Only 258 states -> precompute (m,c) per state once (K1), then run 64 integer
// chains (K3), with bulk I/O kernels for index extraction (K2) and one-hot
// output materialization (K4).

#define V       257
#define B       64
#define L       1024
#define NSTATE  258          // index 257 == ZERO state
#define TOTAL   (B * L * V)  // 16,859,136 floats
#define TOTAL4  (TOTAL / 4)  // exact: divisible by 4

// Scratch (device globals per harness rules; no allocation).
__device__ unsigned g_tab[NSTATE];      // packed (m | c<<16); 0 means "s==0" state
__device__ int      g_xidx[B * L];      // argmax of x rows
__device__ int      g_out [B * L + 1];  // output index per (b,t); -1 = all-zero row (+1 pad)

// ---------------------------------------------------------------------------
// K1: per-state tables. One warp per state: argmax over the two 257-halves of
// W[p,:] + b (ZERO state uses b alone). First-max tie-break == jnp.argmax.
// ---------------------------------------------------------------------------
__global__ void k_tables(const float* __restrict__ W,
                         const float* __restrict__ bb,
                         const int*   __restrict__ inv_table) {
    int p    = blockIdx.x;    // 0..257
    int lane = threadIdx.x;   // 32 threads
    const float* wrow = (p < V) ? (W + (size_t)p * (2 * V)) : nullptr;

    int bestj[2];
    #pragma unroll
    for (int h = 0; h < 2; h++) {
        float bv = -3.402823466e38f;
        int   bj = 0;
        for (int j = lane; j < V; j += 32) {
            int   col = h * V + j;
            float v   = bb[col] + (wrow ? wrow[col] : 0.0f);
            if (v > bv) { bv = v; bj = j; }   // strided j increasing -> first max kept
        }
        #pragma unroll
        for (int off = 16; off; off >>= 1) {
            float ov = __shfl_down_sync(0xffffffffu, bv, off);
            int   oj = __shfl_down_sync(0xffffffffu, bj, off);
            if (ov > bv || (ov == bv && oj < bj)) { bv = ov; bj = oj; }
        }
        bestj[h] = bj;
    }
    if (lane == 0) {
        int l = bestj[0];
        int s = bestj[1];
        int m = inv_table[s];                 // 0 iff s==0
        unsigned e = 0u;
        if (m != 0) {
            int c = (V - (l * m) % V) % V;    // c = (-l*m) mod V, in [0,256]
            e = (unsigned)m | ((unsigned)c << 16);
        }
        g_tab[p] = e;
    }
}

// ---------------------------------------------------------------------------
// K2: extract x_idx. x is an exact one-hot (bits of 0.0f / 1.0f), so scan the
// flat array with float4 loads and record the column of each nonzero.
// ---------------------------------------------------------------------------
__global__ void k_extract(const float* __restrict__ x) {
    int i = blockIdx.x * blockDim.x + threadIdx.x;   // float4 index
    if (i >= TOTAL4) return;
    uint4 v = ((const uint4*)x)[i];
    unsigned vv[4] = { v.x, v.y, v.z, v.w };
    int base = i * 4;
    #pragma unroll
    for (int k = 0; k < 4; k++) {
        if (vv[k] != 0u) {
            int idx = base + k;
            int row = idx / V;                 // magic-multiply division
            int col = idx - row * V;
            g_xidx[row] = col;
        }
    }
}

// ---------------------------------------------------------------------------
// K3: the recurrence. 64 blocks (one per batch), 1 warp each; lane 0 runs the
// 1024-step dependent chain against a shared-memory table.
//
// Doubled table trick: z = x_t*m + c <= 65792; using 256 = -1 (mod 257),
// z mod 257 = (z&255) - (z>>8)  (mod 257), and r = lo - hi + 257 lies in
// [0,512], so a 513-entry doubled table needs NO range correction on the
// critical path. Slot 513 holds the ZERO state's entry.
// Critical path per step: LDS(29) -> unpack(4) -> IMAD(4) -> SHF/AND(4)
// -> IADD3(4) [-> SEL(4) only if any e==0 exists] ~= 45-50 cyc.
// ---------------------------------------------------------------------------
__global__ void k_chain() {
    __shared__ unsigned tabD[514];
    __shared__ int      sx[L];
    int bidx = blockIdx.x;
    int lane = threadIdx.x;

    bool anyz = false;
    for (int i = lane; i < 514; i += 32) {
        int st = (i < V) ? i : ((i == 513) ? V : (i - V));   // 513 -> ZERO (g_tab[257])
        unsigned e = g_tab[st];
        tabD[i] = e;
        anyz |= (e == 0u);
    }
    for (int t = lane; t < L; t += 32) sx[t] = g_xidx[bidx * L + t];
    anyz = __any_sync(0xffffffffu, anyz);
    __syncwarp();

    if (lane == 0) {
        int  idx  = 513;                        // start in ZERO state
        int* outp = g_out + bidx * L;
        if (!anyz) {
            // No state maps to ZERO: drop the select from the critical path.
            #pragma unroll 8
            for (int t = 0; t < L; t++) {
                unsigned e = tabD[idx];
                unsigned z = (unsigned)sx[t] * (e & 0xFFFFu) + (e >> 16);
                int r = (int)(z & 255u) - (int)(z >> 8) + V;   // [0,512]
                idx = r;
                outp[t] = (r >= V) ? (r - V) : r;              // off the chain
            }
        } else {
            #pragma unroll 8
            for (int t = 0; t < L; t++) {
                unsigned e = tabD[idx];
                unsigned z = (unsigned)sx[t] * (e & 0xFFFFu) + (e >> 16);
                int r = (int)(z & 255u) - (int)(z >> 8) + V;
                idx     = (e != 0u) ? r : 513;
                outp[t] = (e != 0u) ? ((r >= V) ? (r - V) : r) : -1;
            }
        }
    }
}

// ---------------------------------------------------------------------------
// K4: materialize the one-hot output. Flat float4 stores (aligned, coalesced),
// comparing each column against g_out[row]. -1 rows stay all-zero.
// ---------------------------------------------------------------------------
__global__ void k_write(float* __restrict__ out) {
    int i = blockIdx.x * blockDim.x + threadIdx.x;   // float4 index
    if (i >= TOTAL4) return;
    int base = i * 4;
    int row  = base / V;
    int col  = base - row * V;
    int oi   = g_out[row];
    float4 o;
    float* op = &o.x;
    #pragma unroll
    for (int k = 0; k < 4; k++) {
        op[k] = (col == oi) ? 1.0f : 0.0f;
        col++;
        if (col == V) { col = 0; row++; oi = g_out[row]; }  // g_out padded by 1
    }
    ((float4*)out)[i] = o;
}

// ---------------------------------------------------------------------------
extern "C" void kernel_launch(void* const* d_in, const int* in_sizes, int n_in,
                              void* d_out, int out_size) {
    const float* x   = (const float*)d_in[0];   // [B, L, V] f32
    const float* W   = (const float*)d_in[1];   // [V, 2V]   f32
    const float* bb  = (const float*)d_in[2];   // [2V]      f32
    const int*   inv = (const int*)  d_in[3];   // [V]       i32

    k_tables<<<NSTATE, 32>>>(W, bb, inv);

    int grid = (TOTAL4 + 255) / 256;
    k_extract<<<grid, 256>>>(x);

    k_chain<<<B, 32>>>();

    k_write<<<grid, 256>>>((float*)d_out);
}

// round 2
// speedup vs baseline: 1.2116x; 1.2116x over previous
#include <cuda_runtime.h>
#include <cstdint>

// DiscreteAutoregressiveFlow: exact one-hot algebra over Z_257.
// V=257 (prime), B=64, L=1024.
//
// next = (x_t * m[p] + c[p]) mod 257 with per-state (m,c) from argmax of W[p]+b.
// Round 2: parallelize the serial chain via segment function-composition
// (k_segmap over all 258 entry states -> k_stitchreplay), and split the
// one-hot output write into zero-fill + scatter.

#define V       257
#define B       64
#define L       1024
#define NSTATE  258          // index 257 == ZERO state
#define SEG     32           // segments per batch
#define SEGLEN  (L / SEG)    // 32 steps per segment
#define TOTAL   (B * L * V)  // 16,859,136 floats
#define TOTAL4  (TOTAL / 4)
#define SENT    (-(1 << 20)) // sentinel for "all-zero output row"

// Scratch (device globals; no allocation allowed).
__device__ unsigned g_tab[NSTATE];              // packed (m | c<<16); 0 => s==0 state
__device__ int      g_xidx[B * L];              // argmax of x rows
__device__ short    g_segmap[B * SEG * NSTATE]; // exit state per (b,seg,entry), 0..257
__device__ int      g_out [B * L];              // output index per (b,t); SENT = zero row

// ---------------------------------------------------------------------------
// K1: per-state tables. One warp per state; first-max tie-break == jnp.argmax.
// ---------------------------------------------------------------------------
__global__ void k_tables(const float* __restrict__ W,
                         const float* __restrict__ bb,
                         const int*   __restrict__ inv_table) {
    int p    = blockIdx.x;    // 0..257
    int lane = threadIdx.x;   // 32
    const float* wrow = (p < V) ? (W + (size_t)p * (2 * V)) : nullptr;

    int bestj[2];
    #pragma unroll
    for (int h = 0; h < 2; h++) {
        float bv = -3.402823466e38f;
        int   bj = 0;
        for (int j = lane; j < V; j += 32) {
            int   col = h * V + j;
            float v   = bb[col] + (wrow ? wrow[col] : 0.0f);
            if (v > bv) { bv = v; bj = j; }
        }
        #pragma unroll
        for (int off = 16; off; off >>= 1) {
            float ov = __shfl_down_sync(0xffffffffu, bv, off);
            int   oj = __shfl_down_sync(0xffffffffu, bj, off);
            if (ov > bv || (ov == bv && oj < bj)) { bv = ov; bj = oj; }
        }
        bestj[h] = bj;
    }
    if (lane == 0) {
        int l = bestj[0];
        int s = bestj[1];
        int m = inv_table[s];                 // 0 iff s==0
        unsigned e = 0u;
        if (m != 0) {
            int c = (V - (l * m) % V) % V;
            e = (unsigned)m | ((unsigned)c << 16);
        }
        g_tab[p] = e;
    }
}

// ---------------------------------------------------------------------------
// K2: extract x_idx (x rows are exact one-hots; find nonzero bits).
// ---------------------------------------------------------------------------
__global__ void k_extract(const float* __restrict__ x) {
    int i = blockIdx.x * blockDim.x + threadIdx.x;
    if (i >= TOTAL4) return;
    uint4 v = ((const uint4*)x)[i];
    unsigned vv[4] = { v.x, v.y, v.z, v.w };
    int base = i * 4;
    #pragma unroll
    for (int k = 0; k < 4; k++) {
        if (vv[k] != 0u) {
            int idx = base + k;
            int row = idx / V;
            int col = idx - row * V;
            g_xidx[row] = col;
        }
    }
}

// ---------------------------------------------------------------------------
// Step macro: doubled-table fold. idx is in [0,512] (doubled rep) or 513 (ZERO).
// tabD[i] = g_tab[i mod 257] for i in [0,512], tabD[513] = g_tab[257] (ZERO).
// z = x*m + c <= 65792; z mod 257 = (z&255) - (z>>8) (mod 257);
// r = lo - hi + 257 in [0,512]: no range correction needed for indexing.
// ---------------------------------------------------------------------------
__device__ __forceinline__ void fill_tabD(unsigned* tabD, int tid, int nthr) {
    for (int i = tid; i < 514; i += nthr) {
        int st = (i < V) ? i : ((i == 513) ? V : (i - V));
        tabD[i] = g_tab[st];
    }
}

// ---------------------------------------------------------------------------
// K3a: segment maps. Block = (segment s, batch b). For every possible entry
// state (0..256, 257=ZERO) walk the 32 steps of this segment; record exit.
// ---------------------------------------------------------------------------
__global__ void k_segmap() {
    __shared__ unsigned tabD[514];
    __shared__ int      sx[SEGLEN];
    int s = blockIdx.x;
    int b = blockIdx.y;
    int tid = threadIdx.x;   // 256

    fill_tabD(tabD, tid, 256);
    if (tid < SEGLEN) sx[tid] = g_xidx[b * L + s * SEGLEN + tid];
    __syncthreads();

    for (int p0 = tid; p0 < NSTATE; p0 += 256) {
        int idx = (p0 == V) ? 513 : p0;
        #pragma unroll
        for (int t = 0; t < SEGLEN; t++) {
            unsigned e = tabD[idx];
            unsigned z = (unsigned)sx[t] * (e & 0xFFFFu) + (e >> 16);
            int r = (int)(z & 255u) - (int)(z >> 8) + V;     // [0,512]
            idx = (e != 0u) ? r : 513;
        }
        int exitc = (idx == 513) ? V : ((idx >= V) ? idx - V : idx);  // 0..257
        g_segmap[(b * SEG + s) * NSTATE + p0] = (short)exitc;
    }
}

// ---------------------------------------------------------------------------
// K3b: stitch + replay. One block per batch. Thread 0 chains the 32 segment
// maps to get each segment's entry state; then 32 threads replay their
// segments with known entries, writing output indices.
// ---------------------------------------------------------------------------
__global__ void k_stitchreplay() {
    __shared__ unsigned tabD[514];
    __shared__ int      sx[L];
    __shared__ short    smap[SEG * NSTATE];
    __shared__ int      entry[SEG];
    int b = blockIdx.x;
    int tid = threadIdx.x;   // 256

    fill_tabD(tabD, tid, 256);
    for (int t = tid; t < L; t += 256) sx[t] = g_xidx[b * L + t];
    for (int i = tid; i < SEG * NSTATE; i += 256) smap[i] = g_segmap[b * SEG * NSTATE + i];
    __syncthreads();

    if (tid == 0) {
        int st = V;  // ZERO
        #pragma unroll
        for (int s = 0; s < SEG; s++) {
            entry[s] = st;
            st = smap[s * NSTATE + st];
        }
    }
    __syncthreads();

    if (tid < SEG) {
        int s = tid;
        int ent = entry[s];
        int idx = (ent == V) ? 513 : ent;
        int* outp = g_out + b * L + s * SEGLEN;
        #pragma unroll
        for (int t = 0; t < SEGLEN; t++) {
            unsigned e = tabD[idx];
            unsigned z = (unsigned)sx[s * SEGLEN + t] * (e & 0xFFFFu) + (e >> 16);
            int r = (int)(z & 255u) - (int)(z >> 8) + V;
            bool ok = (e != 0u);
            idx = ok ? r : 513;
            outp[t] = ok ? ((r >= V) ? r - V : r) : SENT;
        }
    }
}

// ---------------------------------------------------------------------------
// K4a: zero-fill the output (pure STG.128, no per-element logic).
// ---------------------------------------------------------------------------
__global__ void k_zero(float4* __restrict__ out) {
    int i = blockIdx.x * blockDim.x + threadIdx.x;
    if (i < TOTAL4) out[i] = make_float4(0.f, 0.f, 0.f, 0.f);
}

// ---------------------------------------------------------------------------
// K4b: scatter the ones. One thread per (b,t) row.
// ---------------------------------------------------------------------------
__global__ void k_scatter(float* __restrict__ out) {
    int i = blockIdx.x * blockDim.x + threadIdx.x;
    if (i >= B * L) return;
    int oi = g_out[i];
    if (oi >= 0) out[(size_t)i * V + oi] = 1.0f;
}

// ---------------------------------------------------------------------------
extern "C" void kernel_launch(void* const* d_in, const int* in_sizes, int n_in,
                              void* d_out, int out_size) {
    const float* x   = (const float*)d_in[0];   // [B, L, V] f32
    const float* W   = (const float*)d_in[1];   // [V, 2V]   f32
    const float* bb  = (const float*)d_in[2];   // [2V]      f32
    const int*   inv = (const int*)  d_in[3];   // [V]       i32

    int grid4 = (TOTAL4 + 255) / 256;

    k_zero<<<grid4, 256>>>((float4*)d_out);
    k_tables<<<NSTATE, 32>>>(W, bb, inv);
    k_extract<<<grid4, 256>>>(x);
    k_segmap<<<dim3(SEG, B), 256>>>();
    k_stitchreplay<<<B, 256>>>();
    k_scatter<<<(B * L + 255) / 256, 256>>>((float*)d_out);
}

// round 3
// speedup vs baseline: 1.3297x; 1.0975x over previous
#include <cuda_runtime.h>
#include <cstdint>

// DiscreteAutoregressiveFlow: exact one-hot algebra over Z_257.
// next = (x_t * m[p] + c[p]) mod 257, per-state (m,c) from argmax of W[p]+b.
// Round 3: conflict-free x32-replicated SMEM table + ILP-5 chains in k_segmap;
// fused read-x/zero-out kernel; scatter fused into stitch. 4 launches total.

#define V       257
#define B       64
#define L       1024
#define SEG     32
#define SEGLEN  32
#define UNITS   4            // segments per segmap block
#define REP     32           // table replication (bank == lane -> conflict-free)
#define NST     258          // states: 0..256 plus 257 = ZERO
#define TOTAL4  ((B * L * V) / 4)

// Scratch (device globals; no allocation allowed).
__device__ unsigned g_tab[NST];                 // packed m | c<<16; 0 => dead (s==0)
__device__ int      g_xidx[B * L];              // argmax column of each x row
__device__ short    g_segmap[B * SEG * NST];    // exit state per (b,seg,entry)

// ---------------------------------------------------------------------------
// K1: per-state (m,c). 8 warps/block, one warp per state.
// First-max tie-break matches jnp.argmax.
// ---------------------------------------------------------------------------
__global__ void k_tables(const float* __restrict__ W,
                         const float* __restrict__ bb,
                         const int*   __restrict__ inv_table) {
    int p    = blockIdx.x * 8 + (threadIdx.x >> 5);
    int lane = threadIdx.x & 31;
    if (p >= NST) return;
    const float* wrow = (p < V) ? (W + (size_t)p * (2 * V)) : nullptr;

    int bestj[2];
    #pragma unroll
    for (int h = 0; h < 2; h++) {
        float bv = -3.402823466e38f;
        int   bj = 0;
        for (int j = lane; j < V; j += 32) {
            int   col = h * V + j;
            float v   = bb[col] + (wrow ? wrow[col] : 0.0f);
            if (v > bv) { bv = v; bj = j; }
        }
        #pragma unroll
        for (int off = 16; off; off >>= 1) {
            float ov = __shfl_down_sync(0xffffffffu, bv, off);
            int   oj = __shfl_down_sync(0xffffffffu, bj, off);
            if (ov > bv || (ov == bv && oj < bj)) { bv = ov; bj = oj; }
        }
        bestj[h] = bj;
    }
    if (lane == 0) {
        int l = bestj[0];
        int s = bestj[1];
        int m = inv_table[s];                 // 0 iff s==0
        unsigned e = 0u;
        if (m != 0) {
            int c = (V - (l * m) % V) % V;
            e = (unsigned)m | ((unsigned)c << 16);
        }
        g_tab[p] = e;
    }
}

// ---------------------------------------------------------------------------
// K2: fused I/O. One streaming pass: read x (float4), write zeros to out
// (float4), record the column of each row's 1.0f into g_xidx.
// ---------------------------------------------------------------------------
__global__ void k_io(const uint4* __restrict__ x, uint4* __restrict__ out) {
    int i = blockIdx.x * blockDim.x + threadIdx.x;
    if (i >= TOTAL4) return;
    uint4 v = x[i];
    out[i] = make_uint4(0u, 0u, 0u, 0u);
    if (v.x | v.y | v.z | v.w) {
        unsigned a[4] = { v.x, v.y, v.z, v.w };
        int base = i * 4;
        #pragma unroll
        for (int k = 0; k < 4; k++) {
            if (a[k] != 0u) {
                int idx = base + k;
                int row = idx / V;
                g_xidx[row] = idx - row * V;
            }
        }
    }
}

// ---------------------------------------------------------------------------
// Table-slot convention (doubled table):
//   slots 0..512 hold state (slot mod 257); slot 513 holds ZERO (state 257).
//   step: z = x*m + c (<= 65792); z mod 257 == (z&255) - (z>>8) (mod 257);
//   w = lo - hi + 257 is in [0,512] -> direct slot, no range fix needed.
//   Dead entry (e==0) forces slot 513.
// ---------------------------------------------------------------------------
__device__ __forceinline__ int slot_state(int slot) {
    return (slot == 513) ? V : ((slot >= V) ? slot - V : slot);
}

// ---------------------------------------------------------------------------
// K3a: segment maps. Block = (4 segments, batch). Table replicated x32 so the
// random gather is bank-conflict-free (bank == lane). Each thread runs 5
// interleaved chains (ILP): state tid across units 0..3, plus one redundant
// leftover chain covering states 256/257 (identical values, benign races).
// ---------------------------------------------------------------------------
extern __shared__ unsigned s_tab[];   // 514 * REP words = 65792 B (dynamic)

__global__ void __launch_bounds__(256) k_segmap() {
    __shared__ __align__(16) int sxs[UNITS * SEGLEN];   // [t][unit]
    int tid = threadIdx.x;
    int b   = blockIdx.y;
    int s0  = blockIdx.x * UNITS;

    for (int i = tid; i < 514 * REP; i += 256) {
        int slot = i >> 5;                                // i / REP
        int st = (slot < V) ? slot : ((slot == 513) ? V : slot - V);
        s_tab[i] = g_tab[st];
    }
    for (int i = tid; i < UNITS * SEGLEN; i += 256) {
        int t = i >> 2, u = i & 3;
        sxs[i] = g_xidx[b * L + (s0 + u) * SEGLEN + t];
    }
    __syncthreads();

    int rep = tid & 31;                 // == lane -> conflict-free column
    int p4  = 256 + (tid & 1);          // leftover states 256/257
    int un4 = (tid >> 1) & 3;

    int idx[5];
    #pragma unroll
    for (int j = 0; j < 4; j++) idx[j] = tid;            // state tid -> slot tid
    idx[4] = (p4 == V) ? 513 : p4;

    #pragma unroll 4
    for (int t = 0; t < SEGLEN; t++) {
        uint4 xv = *(const uint4*)&sxs[t * 4];           // broadcast LDS.128
        unsigned x4 = (un4 & 2) ? ((un4 & 1) ? xv.w : xv.z)
                                : ((un4 & 1) ? xv.y : xv.x);
        unsigned xs[5] = { xv.x, xv.y, xv.z, xv.w, x4 };
        #pragma unroll
        for (int j = 0; j < 5; j++) {
            unsigned e = s_tab[idx[j] * REP + rep];
            unsigned z = xs[j] * (e & 0xFFFFu) + (e >> 16);
            int w = (int)(z & 255u) - (int)(z >> 8) + V;  // slot in [0,512]
            idx[j] = (e != 0u) ? w : 513;
        }
    }

    short* seg0 = g_segmap + (size_t)(b * SEG + s0) * NST;
    #pragma unroll
    for (int j = 0; j < 4; j++)
        seg0[j * NST + tid] = (short)slot_state(idx[j]);
    seg0[un4 * NST + p4] = (short)slot_state(idx[4]);     // redundant, same value
}

// ---------------------------------------------------------------------------
// K3b: stitch + replay + scatter. One block per batch: thread 0 chains the 32
// segment maps; 32 threads replay their segments and write the 1.0f's
// directly into the (already zeroed) output.
// ---------------------------------------------------------------------------
__global__ void k_stitch(float* __restrict__ out) {
    __shared__ unsigned tabD[514];
    __shared__ int      sx[L];
    __shared__ short    smap[SEG * NST];
    __shared__ short    entry[SEG];
    int b = blockIdx.x;
    int tid = threadIdx.x;   // 256

    for (int i = tid; i < 514; i += 256) {
        int st = (i < V) ? i : ((i == 513) ? V : i - V);
        tabD[i] = g_tab[st];
    }
    for (int t = tid; t < L; t += 256) sx[t] = g_xidx[b * L + t];
    for (int i = tid; i < SEG * NST; i += 256)
        smap[i] = g_segmap[(size_t)b * SEG * NST + i];
    __syncthreads();

    if (tid == 0) {
        int st = V;   // ZERO
        #pragma unroll
        for (int s = 0; s < SEG; s++) { entry[s] = (short)st; st = smap[s * NST + st]; }
    }
    __syncthreads();

    if (tid < SEG) {
        int s   = tid;
        int ent = entry[s];
        int idx = (ent == V) ? 513 : ent;
        float* orow = out + (size_t)(b * L + s * SEGLEN) * V;
        #pragma unroll 8
        for (int t = 0; t < SEGLEN; t++) {
            unsigned e = tabD[idx];
            unsigned z = (unsigned)sx[s * SEGLEN + t] * (e & 0xFFFFu) + (e >> 16);
            int w = (int)(z & 255u) - (int)(z >> 8) + V;
            bool ok = (e != 0u);
            idx = ok ? w : 513;
            if (ok) {
                int oi = (w >= V) ? w - V : w;
                orow[(size_t)t * V + oi] = 1.0f;
            }
        }
    }
}

// ---------------------------------------------------------------------------
extern "C" void kernel_launch(void* const* d_in, const int* in_sizes, int n_in,
                              void* d_out, int out_size) {
    const float* x   = (const float*)d_in[0];   // [B, L, V] f32
    const float* W   = (const float*)d_in[1];   // [V, 2V]   f32
    const float* bb  = (const float*)d_in[2];   // [2V]      f32
    const int*   inv = (const int*)  d_in[3];   // [V]       i32

    // Opt in to 64KB+ dynamic SMEM for the replicated table (host-side,
    // capture-safe, idempotent).
    cudaFuncSetAttribute(k_segmap, cudaFuncAttributeMaxDynamicSharedMemorySize,
                         514 * REP * 4);

    k_tables<<<(NST + 7) / 8, 256>>>(W, bb, inv);
    k_io<<<(TOTAL4 + 255) / 256, 256>>>((const uint4*)x, (uint4*)d_out);
    k_segmap<<<dim3(SEG / UNITS, B), 256, 514 * REP * 4>>>();
    k_stitch<<<B, 256>>>((float*)d_out);
}

// round 4
// speedup vs baseline: 1.3920x; 1.0468x over previous
#include <cuda_runtime.h>
#include <cstdint>

// DiscreteAutoregressiveFlow: exact one-hot algebra over Z_257.
// next = (x_t * m[p] + c[p]) mod 257, per-state (m,c) from argmax of W[p]+b.
// Round 4: fix k_stitch's scalar U16 global loads (uint4 everywhere),
// otherwise keep the r3 structure (4 launches).

#define V       257
#define B       64
#define L       1024
#define SEG     32
#define SEGLEN  32
#define UNITS   4            // segments per segmap block
#define REP     32           // table replication (bank == lane -> conflict-free)
#define NST     258          // states: 0..256 plus 257 = ZERO
#define TOTAL4  ((B * L * V) / 4)

// Scratch (device globals; no allocation allowed).
__device__ unsigned g_tab[NST];                              // m | c<<16; 0 => dead
__device__ __align__(16) int   g_xidx[B * L];                // argmax col per x row
__device__ __align__(16) short g_segmap[B * SEG * NST];      // exit state maps

// ---------------------------------------------------------------------------
// K1: per-state (m,c). 8 warps/block, one warp per state.
// First-max tie-break matches jnp.argmax.
// ---------------------------------------------------------------------------
__global__ void k_tables(const float* __restrict__ W,
                         const float* __restrict__ bb,
                         const int*   __restrict__ inv_table) {
    int p    = blockIdx.x * 8 + (threadIdx.x >> 5);
    int lane = threadIdx.x & 31;
    if (p >= NST) return;
    const float* wrow = (p < V) ? (W + (size_t)p * (2 * V)) : nullptr;

    int bestj[2];
    #pragma unroll
    for (int h = 0; h < 2; h++) {
        float bv = -3.402823466e38f;
        int   bj = 0;
        for (int j = lane; j < V; j += 32) {
            int   col = h * V + j;
            float v   = bb[col] + (wrow ? wrow[col] : 0.0f);
            if (v > bv) { bv = v; bj = j; }
        }
        #pragma unroll
        for (int off = 16; off; off >>= 1) {
            float ov = __shfl_down_sync(0xffffffffu, bv, off);
            int   oj = __shfl_down_sync(0xffffffffu, bj, off);
            if (ov > bv || (ov == bv && oj < bj)) { bv = ov; bj = oj; }
        }
        bestj[h] = bj;
    }
    if (lane == 0) {
        int l = bestj[0];
        int s = bestj[1];
        int m = inv_table[s];                 // 0 iff s==0
        unsigned e = 0u;
        if (m != 0) {
            int c = (V - (l * m) % V) % V;
            e = (unsigned)m | ((unsigned)c << 16);
        }
        g_tab[p] = e;
    }
}

// ---------------------------------------------------------------------------
// K2: fused I/O. One streaming pass: read x (float4), write zeros to out
// (float4), record the column of each row's 1.0f into g_xidx.
// ---------------------------------------------------------------------------
__global__ void k_io(const uint4* __restrict__ x, uint4* __restrict__ out) {
    int i = blockIdx.x * blockDim.x + threadIdx.x;
    if (i >= TOTAL4) return;
    uint4 v = x[i];
    out[i] = make_uint4(0u, 0u, 0u, 0u);
    if (v.x | v.y | v.z | v.w) {
        unsigned a[4] = { v.x, v.y, v.z, v.w };
        int base = i * 4;
        #pragma unroll
        for (int k = 0; k < 4; k++) {
            if (a[k] != 0u) {
                int idx = base + k;
                int row = idx / V;
                g_xidx[row] = idx - row * V;
            }
        }
    }
}

// ---------------------------------------------------------------------------
// Doubled-table convention: slots 0..512 alias state (slot mod 257);
// slot 513 = ZERO. step: z = x*m + c <= 65792; z mod 257 == (z&255)-(z>>8)
// (mod 257); w = lo - hi + 257 in [0,512] -> direct slot. Dead (e==0) -> 513.
// ---------------------------------------------------------------------------
__device__ __forceinline__ int slot_state(int slot) {
    return (slot == 513) ? V : ((slot >= V) ? slot - V : slot);
}

// ---------------------------------------------------------------------------
// K3a: segment maps. Block = (4 segments, batch). x32-replicated SMEM table
// (bank == lane -> conflict-free). ILP-5 chains per thread.
// ---------------------------------------------------------------------------
extern __shared__ unsigned s_tab[];   // 514 * REP words = 65792 B (dynamic)

__global__ void __launch_bounds__(256) k_segmap() {
    __shared__ __align__(16) int sxs[UNITS * SEGLEN];   // [t][unit]
    int tid = threadIdx.x;
    int b   = blockIdx.y;
    int s0  = blockIdx.x * UNITS;

    for (int i = tid; i < 514 * REP; i += 256) {
        int slot = i >> 5;
        int st = (slot < V) ? slot : ((slot == 513) ? V : slot - V);
        s_tab[i] = g_tab[st];
    }
    // UNITS*SEGLEN = 128 ints = 32 uint4; layout sxs[t*4+u].
    if (tid < 32) {
        const int* src = g_xidx + b * L + s0 * SEGLEN;
        int t = tid; // each thread fills sxs[t*4 .. t*4+3]
        int4 w;
        w.x = src[0 * SEGLEN + t];
        w.y = src[1 * SEGLEN + t];
        w.z = src[2 * SEGLEN + t];
        w.w = src[3 * SEGLEN + t];
        *(int4*)&sxs[t * 4] = w;
    }
    __syncthreads();

    int rep = tid & 31;                 // == lane -> conflict-free column
    int p4  = 256 + (tid & 1);          // leftover states 256/257
    int un4 = (tid >> 1) & 3;

    int idx[5];
    #pragma unroll
    for (int j = 0; j < 4; j++) idx[j] = tid;            // state tid -> slot tid
    idx[4] = (p4 == V) ? 513 : p4;

    #pragma unroll 4
    for (int t = 0; t < SEGLEN; t++) {
        uint4 xv = *(const uint4*)&sxs[t * 4];           // broadcast LDS.128
        unsigned x4 = (un4 & 2) ? ((un4 & 1) ? xv.w : xv.z)
                                : ((un4 & 1) ? xv.y : xv.x);
        unsigned xs[5] = { xv.x, xv.y, xv.z, xv.w, x4 };
        #pragma unroll
        for (int j = 0; j < 5; j++) {
            unsigned e = s_tab[idx[j] * REP + rep];
            unsigned z = xs[j] * (e & 0xFFFFu) + (e >> 16);
            int w = (int)(z & 255u) - (int)(z >> 8) + V;  // slot in [0,512]
            idx[j] = (e != 0u) ? w : 513;
        }
    }

    short* seg0 = g_segmap + (size_t)(b * SEG + s0) * NST;
    #pragma unroll
    for (int j = 0; j < 4; j++)
        seg0[j * NST + tid] = (short)slot_state(idx[j]);
    seg0[un4 * NST + p4] = (short)slot_state(idx[4]);     // redundant, same value
}

// ---------------------------------------------------------------------------
// K3b: stitch + replay + scatter. One block per batch. ALL global loads are
// uint4 (this was the r3 bottleneck: scalar LDG.U16 on a 64-block grid).
// ---------------------------------------------------------------------------
#define SMAP_U4 ((SEG * NST * 2) / 16)   // 1032 uint4 = 16512 B

__global__ void k_stitch(float* __restrict__ out) {
    __shared__ unsigned tabD[514];
    __shared__ __align__(16) int   sx[L];
    __shared__ __align__(16) short smap[SEG * NST];
    __shared__ short entry[SEG];
    int b = blockIdx.x;
    int tid = threadIdx.x;   // 256

    // table (tiny, L2-resident broadcast)
    for (int i = tid; i < 514; i += 256) {
        int st = (i < V) ? i : ((i == 513) ? V : i - V);
        tabD[i] = g_tab[st];
    }
    // sx: 1024 ints = 256 uint4, one per thread
    {
        const uint4* src = (const uint4*)(g_xidx + b * L);
        ((uint4*)sx)[tid] = src[tid];
    }
    // smap: 1032 uint4
    {
        const uint4* src = (const uint4*)(g_segmap + (size_t)b * SEG * NST);
        uint4* dst = (uint4*)smap;
        #pragma unroll
        for (int k = 0; k < 4; k++) dst[tid + 256 * k] = src[tid + 256 * k];
        if (tid < SMAP_U4 - 1024) dst[1024 + tid] = src[1024 + tid];
    }
    __syncthreads();

    if (tid == 0) {
        int st = V;   // ZERO
        #pragma unroll
        for (int s = 0; s < SEG; s++) { entry[s] = (short)st; st = smap[s * NST + st]; }
    }
    __syncthreads();

    if (tid < SEG) {
        int s   = tid;
        int ent = entry[s];
        int idx = (ent == V) ? 513 : ent;
        float* orow = out + (size_t)(b * L + s * SEGLEN) * V;
        #pragma unroll 8
        for (int t = 0; t < SEGLEN; t++) {
            unsigned e = tabD[idx];
            unsigned z = (unsigned)sx[s * SEGLEN + t] * (e & 0xFFFFu) + (e >> 16);
            int w = (int)(z & 255u) - (int)(z >> 8) + V;
            bool ok = (e != 0u);
            idx = ok ? w : 513;
            if (ok) {
                int oi = (w >= V) ? w - V : w;
                orow[(size_t)t * V + oi] = 1.0f;
            }
        }
    }
}

// ---------------------------------------------------------------------------
extern "C" void kernel_launch(void* const* d_in, const int* in_sizes, int n_in,
                              void* d_out, int out_size) {
    const float* x   = (const float*)d_in[0];   // [B, L, V] f32
    const float* W   = (const float*)d_in[1];   // [V, 2V]   f32
    const float* bb  = (const float*)d_in[2];   // [2V]      f32
    const int*   inv = (const int*)  d_in[3];   // [V]       i32

    cudaFuncSetAttribute(k_segmap, cudaFuncAttributeMaxDynamicSharedMemorySize,
                         514 * REP * 4);

    k_tables<<<(NST + 7) / 8, 256>>>(W, bb, inv);
    k_io<<<(TOTAL4 + 255) / 256, 256>>>((const uint4*)x, (uint4*)d_out);
    k_segmap<<<dim3(SEG / UNITS, B), 256, 514 * REP * 4>>>();
    k_stitch<<<B, 256>>>((float*)d_out);
}

// round 5
// speedup vs baseline: 1.6952x; 1.2178x over previous
#include <cuda_runtime.h>
#include <cstdint>

// DiscreteAutoregressiveFlow: exact one-hot algebra over Z_257.
// next = (x_t * m[p] + c[p]) mod 257, per-state (m,c) from argmax of W[p]+b.
// Round 5: 3 fused launches. k_pre = tables + x-extract; k_mid = segmap
// overlapped with output zero-fill (block-role split); k_fin = stitch +
// replay + scatter with conflict-free replicated table.

#define V       257
#define B       64
#define L       1024
#define SEG     32
#define SEGLEN  32
#define UNITS   8            // segments per segmap block
#define REP     32           // table replication (bank == lane)
#define NST     258          // states 0..256 plus 257 = ZERO
#define TOTAL4  ((B * L * V) / 4)        // 4,214,784 uint4
#define HALF4   (TOTAL4 / 2)             // 2,107,392
#define XBLK    (HALF4 / 256)            // 8232 extract blocks (exact)
#define TBLK    33                       // table blocks (264 warps >= 258)
#define SEGBLK  ((SEG / UNITS) * B)      // 256 segmap blocks
#define ZBLK    (TOTAL4 / 1024)          // 4116 zero blocks (exact)

// Scratch (device globals; no allocation allowed).
__device__ unsigned g_tab[NST];                          // m | c<<16; 0 => dead
__device__ __align__(16) int   g_xidx[B * L];
__device__ __align__(16) short g_segmap[B * SEG * NST];

// ---------------------------------------------------------------------------
// Doubled-table convention: slots 0..512 alias state (slot mod 257); slot 513
// = ZERO. step: z = x*m + c <= 65792; z mod 257 == (z&255) - (z>>8) (mod 257);
// w = lo - hi + 257 in [0,512] -> direct slot. Dead entry (e==0) -> slot 513.
// ---------------------------------------------------------------------------
__device__ __forceinline__ int slot_state(int slot) {
    return (slot == 513) ? V : ((slot >= V) ? slot - V : slot);
}
__device__ __forceinline__ int slot_src(int i) {        // slot -> g_tab index
    return (i < V) ? i : ((i == 513) ? V : i - V);
}

// ---------------------------------------------------------------------------
// K_PRE: blocks [0, TBLK): per-state (m,c) tables (one warp per state,
// first-max tie-break == jnp.argmax). Blocks [TBLK, ...): extract x argmax
// columns, 2 uint4 per thread (split halves keep full coalescing).
// ---------------------------------------------------------------------------
__global__ void __launch_bounds__(256) k_pre(const float* __restrict__ W,
                                             const float* __restrict__ bb,
                                             const int*   __restrict__ inv_table,
                                             const uint4* __restrict__ x) {
    int bid = blockIdx.x;
    int tid = threadIdx.x;

    if (bid < TBLK) {
        int p    = bid * 8 + (tid >> 5);
        int lane = tid & 31;
        if (p >= NST) return;
        const float* wrow = (p < V) ? (W + (size_t)p * (2 * V)) : nullptr;
        int bestj[2];
        #pragma unroll
        for (int h = 0; h < 2; h++) {
            float bv = -3.402823466e38f;
            int   bj = 0;
            for (int j = lane; j < V; j += 32) {
                int   col = h * V + j;
                float v   = bb[col] + (wrow ? wrow[col] : 0.0f);
                if (v > bv) { bv = v; bj = j; }
            }
            #pragma unroll
            for (int off = 16; off; off >>= 1) {
                float ov = __shfl_down_sync(0xffffffffu, bv, off);
                int   oj = __shfl_down_sync(0xffffffffu, bj, off);
                if (ov > bv || (ov == bv && oj < bj)) { bv = ov; bj = oj; }
            }
            bestj[h] = bj;
        }
        if (lane == 0) {
            int l = bestj[0], s = bestj[1];
            int m = inv_table[s];                 // 0 iff s==0
            unsigned e = 0u;
            if (m != 0) {
                int c = (V - (l * m) % V) % V;
                e = (unsigned)m | ((unsigned)c << 16);
            }
            g_tab[p] = e;
        }
        return;
    }

    // extract
    int i0 = (bid - TBLK) * 256 + tid;
    #pragma unroll
    for (int h = 0; h < 2; h++) {
        int i = i0 + h * HALF4;
        uint4 v = x[i];
        if (v.x | v.y | v.z | v.w) {
            unsigned a[4] = { v.x, v.y, v.z, v.w };
            int base = i * 4;
            #pragma unroll
            for (int k = 0; k < 4; k++) {
                if (a[k] != 0u) {
                    int idx = base + k;
                    int row = idx / V;
                    g_xidx[row] = idx - row * V;
                }
            }
        }
    }
}

// ---------------------------------------------------------------------------
// K_MID: blocks [0, SEGBLK): segment maps (latency/LDS-bound, ~no DRAM).
// Blocks [SEGBLK, ...): zero-fill d_out (pure STG.128 stream). The two roles
// co-reside, overlapping segmap compute under the 67MB store stream.
// ---------------------------------------------------------------------------
extern __shared__ unsigned s_tab[];   // 514 * REP = 65792 B dynamic

__global__ void __launch_bounds__(256) k_mid(uint4* __restrict__ out) {
    int bid = blockIdx.x;
    int tid = threadIdx.x;

    if (bid >= SEGBLK) {
        // zero-fill: 4 coalesced uint4 per thread, exact coverage
        int base = (bid - SEGBLK) * 1024 + tid;
        uint4 z = make_uint4(0u, 0u, 0u, 0u);
        #pragma unroll
        for (int k = 0; k < 4; k++) out[base + k * 256] = z;
        return;
    }

    // ---- segmap ----
    __shared__ unsigned tabS[514];
    __shared__ __align__(16) int sxs[UNITS * SEGLEN];   // [t*8 + u]
    int b  = bid >> 2;
    int s0 = (bid & 3) * UNITS;

    for (int i = tid; i < 514; i += 256) tabS[i] = g_tab[slot_src(i)];
    {   // sxs: u = warp, t = lane -> coalesced LDG
        int u = tid >> 5, t = tid & 31;
        sxs[t * 8 + u] = g_xidx[b * L + (s0 + u) * SEGLEN + t];
    }
    __syncthreads();
    for (int i = tid; i < 514 * REP; i += 256) s_tab[i] = tabS[i >> 5];
    __syncthreads();

    int rep = tid & 31;
    int p4  = 256 + (tid & 1);          // leftover states 256/257 (redundant xN)
    int un8 = (tid >> 1) & 7;

    int idx[9];
    #pragma unroll
    for (int j = 0; j < 8; j++) idx[j] = tid;           // state tid -> slot tid
    idx[8] = (p4 == V) ? 513 : p4;

    #pragma unroll 4
    for (int t = 0; t < SEGLEN; t++) {
        uint4 xv0 = *(const uint4*)&sxs[t * 8];
        uint4 xv1 = *(const uint4*)&sxs[t * 8 + 4];
        unsigned xs[9] = { xv0.x, xv0.y, xv0.z, xv0.w,
                           xv1.x, xv1.y, xv1.z, xv1.w,
                           (unsigned)sxs[t * 8 + un8] };
        #pragma unroll
        for (int j = 0; j < 9; j++) {
            unsigned e = s_tab[idx[j] * REP + rep];
            unsigned z = xs[j] * (e & 0xFFFFu) + (e >> 16);
            int w = (int)(z & 255u) - (int)(z >> 8) + V;
            idx[j] = (e != 0u) ? w : 513;
        }
    }

    short* seg0 = g_segmap + (size_t)(b * SEG + s0) * NST;
    #pragma unroll
    for (int j = 0; j < 8; j++)
        seg0[j * NST + tid] = (short)slot_state(idx[j]);
    seg0[un8 * NST + p4] = (short)slot_state(idx[8]);    // redundant, same value
}

// ---------------------------------------------------------------------------
// K_FIN: stitch + replay + scatter. One block per batch. uint4 global loads;
// replicated table makes the replay gather conflict-free.
// ---------------------------------------------------------------------------
#define SMAP_U4 ((SEG * NST * 2) / 16)   // 1032

__global__ void __launch_bounds__(256) k_fin(float* __restrict__ out) {
    __shared__ unsigned tabS[514];
    __shared__ __align__(16) int   sx[L];
    __shared__ __align__(16) short smap[SEG * NST];
    __shared__ short entry[SEG];
    int b = blockIdx.x;
    int tid = threadIdx.x;

    for (int i = tid; i < 514; i += 256) tabS[i] = g_tab[slot_src(i)];
    ((uint4*)sx)[tid] = ((const uint4*)(g_xidx + b * L))[tid];
    {
        const uint4* src = (const uint4*)(g_segmap + (size_t)b * SEG * NST);
        uint4* dst = (uint4*)smap;
        #pragma unroll
        for (int k = 0; k < 4; k++) dst[tid + 256 * k] = src[tid + 256 * k];
        if (tid < SMAP_U4 - 1024) dst[1024 + tid] = src[1024 + tid];
    }
    __syncthreads();
    for (int i = tid; i < 514 * REP; i += 256) s_tab[i] = tabS[i >> 5];

    if (tid == 0) {
        int st = V;   // ZERO
        #pragma unroll
        for (int s = 0; s < SEG; s++) { entry[s] = (short)st; st = smap[s * NST + st]; }
    }
    __syncthreads();

    if (tid < SEG) {
        int s   = tid;                   // lane == tid -> conflict-free column
        int ent = entry[s];
        int idx = (ent == V) ? 513 : ent;
        float* orow = out + (size_t)(b * L + s * SEGLEN) * V;
        #pragma unroll 8
        for (int t = 0; t < SEGLEN; t++) {
            unsigned e = s_tab[idx * REP + tid];
            unsigned z = (unsigned)sx[s * SEGLEN + t] * (e & 0xFFFFu) + (e >> 16);
            int w = (int)(z & 255u) - (int)(z >> 8) + V;
            bool ok = (e != 0u);
            idx = ok ? w : 513;
            if (ok) {
                int oi = (w >= V) ? w - V : w;
                orow[(size_t)t * V + oi] = 1.0f;
            }
        }
    }
}

// ---------------------------------------------------------------------------
extern "C" void kernel_launch(void* const* d_in, const int* in_sizes, int n_in,
                              void* d_out, int out_size) {
    const float* x   = (const float*)d_in[0];   // [B, L, V] f32
    const float* W   = (const float*)d_in[1];   // [V, 2V]   f32
    const float* bb  = (const float*)d_in[2];   // [2V]      f32
    const int*   inv = (const int*)  d_in[3];   // [V]       i32

    const int dynsmem = 514 * REP * 4;          // 65792 B
    cudaFuncSetAttribute(k_mid, cudaFuncAttributeMaxDynamicSharedMemorySize, dynsmem);
    cudaFuncSetAttribute(k_fin, cudaFuncAttributeMaxDynamicSharedMemorySize, dynsmem);

    k_pre<<<TBLK + XBLK, 256>>>(W, bb, inv, (const uint4*)x);
    k_mid<<<SEGBLK + ZBLK, 256, dynsmem>>>((uint4*)d_out);
    k_fin<<<B, 256, dynsmem>>>((float*)d_out);
}

// round 6
// speedup vs baseline: 1.8033x; 1.0638x over previous
#include <cuda_runtime.h>
#include <cstdint>

// DiscreteAutoregressiveFlow: exact one-hot algebra over Z_257.
// next = (x_t * m[p] + c[p]) mod 257, per-state (m,c) from argmax of W[p]+b.
// Round 6: mix the 67MB read (extract) and 67MB write (zero-fill) streams in
// ONE launch (k_A, block-role interleaved) + standalone segmap (k_B) + slim
// stitch/replay/scatter (k_fin, no table replication).

#define V       257
#define B       64
#define L       1024
#define SEG     32
#define SEGLEN  32
#define UNITS   8            // segments per segmap block
#define REP     32           // table replication (bank == lane), segmap only
#define NST     258          // states 0..256 plus 257 = ZERO
#define TOTAL4  ((B * L * V) / 4)        // 4,214,784 uint4
#define TBLK    33                       // table blocks (264 warps >= 258)
#define MIXB    (TOTAL4 / 1024)          // 4116 extract blocks == 4116 zero blocks
#define SEGBLK  ((SEG / UNITS) * B)      // 256 segmap blocks

// Scratch (device globals; no allocation allowed).
__device__ unsigned g_tab[NST];                          // m | c<<16; 0 => dead
__device__ __align__(16) int   g_xidx[B * L];
__device__ __align__(16) short g_segmap[B * SEG * NST];

// ---------------------------------------------------------------------------
// Doubled-table convention: slots 0..512 alias state (slot mod 257); slot 513
// = ZERO. step: z = x*m + c <= 65792; z mod 257 == (z&255) - (z>>8) (mod 257);
// w = lo - hi + 257 in [0,512] -> direct slot. Dead entry (e==0) -> slot 513.
// ---------------------------------------------------------------------------
__device__ __forceinline__ int slot_state(int slot) {
    return (slot == 513) ? V : ((slot >= V) ? slot - V : slot);
}
__device__ __forceinline__ int slot_src(int i) {        // slot -> g_tab index
    return (i < V) ? i : ((i == 513) ? V : i - V);
}

// ---------------------------------------------------------------------------
// K_A: three block roles in one launch so the read stream (x extract), the
// write stream (zero-fill of out) and the tiny tables job share the chip and
// the HBM pipe concurrently.
//   blocks [0, TBLK):        per-state (m,c) tables (warp per state)
//   blocks TBLK+even:        extract (4 x uint4 loads per thread)
//   blocks TBLK+odd:         zero-fill (4 x uint4 stores per thread)
// ---------------------------------------------------------------------------
__global__ void __launch_bounds__(256) k_A(const float* __restrict__ W,
                                           const float* __restrict__ bb,
                                           const int*   __restrict__ inv_table,
                                           const uint4* __restrict__ x,
                                           uint4*       __restrict__ out) {
    int bid = blockIdx.x;
    int tid = threadIdx.x;

    if (bid < TBLK) {
        int p    = bid * 8 + (tid >> 5);
        int lane = tid & 31;
        if (p >= NST) return;
        const float* wrow = (p < V) ? (W + (size_t)p * (2 * V)) : nullptr;
        int bestj[2];
        #pragma unroll
        for (int h = 0; h < 2; h++) {
            float bv = -3.402823466e38f;
            int   bj = 0;
            for (int j = lane; j < V; j += 32) {
                int   col = h * V + j;
                float v   = bb[col] + (wrow ? wrow[col] : 0.0f);
                if (v > bv) { bv = v; bj = j; }     // first-max == jnp.argmax
            }
            #pragma unroll
            for (int off = 16; off; off >>= 1) {
                float ov = __shfl_down_sync(0xffffffffu, bv, off);
                int   oj = __shfl_down_sync(0xffffffffu, bj, off);
                if (ov > bv || (ov == bv && oj < bj)) { bv = ov; bj = oj; }
            }
            bestj[h] = bj;
        }
        if (lane == 0) {
            int l = bestj[0], s = bestj[1];
            int m = inv_table[s];                 // 0 iff s==0
            unsigned e = 0u;
            if (m != 0) {
                int c = (V - (l * m) % V) % V;
                e = (unsigned)m | ((unsigned)c << 16);
            }
            g_tab[p] = e;
        }
        return;
    }

    int m    = bid - TBLK;
    int unit = m >> 1;
    int base = unit * 1024 + tid;

    if (m & 1) {
        // zero-fill: 4 coalesced uint4 stores
        uint4 z = make_uint4(0u, 0u, 0u, 0u);
        #pragma unroll
        for (int k = 0; k < 4; k++) out[base + k * 256] = z;
        return;
    }

    // extract: 4 coalesced uint4 loads (MLP=4), rare inner path finds the 1.0f
    uint4 v[4];
    #pragma unroll
    for (int k = 0; k < 4; k++) v[k] = x[base + k * 256];
    #pragma unroll
    for (int k = 0; k < 4; k++) {
        if (v[k].x | v[k].y | v[k].z | v[k].w) {
            unsigned a[4] = { v[k].x, v[k].y, v[k].z, v[k].w };
            int eb = (base + k * 256) * 4;
            #pragma unroll
            for (int j = 0; j < 4; j++) {
                if (a[j] != 0u) {
                    int idx = eb + j;
                    int row = idx / V;
                    g_xidx[row] = idx - row * V;
                }
            }
        }
    }
}

// ---------------------------------------------------------------------------
// K_B: segment maps. Block = (8 segments, batch). x32-replicated SMEM table
// (bank == lane -> conflict-free), ILP-9 chains per thread.
// ---------------------------------------------------------------------------
extern __shared__ unsigned s_tab[];   // 514 * REP = 65792 B dynamic

__global__ void __launch_bounds__(256) k_B() {
    __shared__ unsigned tabS[514];
    __shared__ __align__(16) int sxs[UNITS * SEGLEN];   // [t*8 + u]
    int bid = blockIdx.x;
    int tid = threadIdx.x;
    int b  = bid >> 2;
    int s0 = (bid & 3) * UNITS;

    for (int i = tid; i < 514; i += 256) tabS[i] = g_tab[slot_src(i)];
    {   // sxs: u = warp, t = lane -> coalesced LDG
        int u = tid >> 5, t = tid & 31;
        sxs[t * 8 + u] = g_xidx[b * L + (s0 + u) * SEGLEN + t];
    }
    __syncthreads();
    for (int i = tid; i < 514 * REP; i += 256) s_tab[i] = tabS[i >> 5];
    __syncthreads();

    int rep = tid & 31;
    int p4  = 256 + (tid & 1);          // leftover states 256/257 (redundant xN)
    int un8 = (tid >> 1) & 7;

    int idx[9];
    #pragma unroll
    for (int j = 0; j < 8; j++) idx[j] = tid;           // state tid -> slot tid
    idx[8] = (p4 == V) ? 513 : p4;

    #pragma unroll 4
    for (int t = 0; t < SEGLEN; t++) {
        uint4 xv0 = *(const uint4*)&sxs[t * 8];
        uint4 xv1 = *(const uint4*)&sxs[t * 8 + 4];
        unsigned xs[9] = { xv0.x, xv0.y, xv0.z, xv0.w,
                           xv1.x, xv1.y, xv1.z, xv1.w,
                           (unsigned)sxs[t * 8 + un8] };
        #pragma unroll
        for (int j = 0; j < 9; j++) {
            unsigned e = s_tab[idx[j] * REP + rep];
            unsigned z = xs[j] * (e & 0xFFFFu) + (e >> 16);
            int w = (int)(z & 255u) - (int)(z >> 8) + V;
            idx[j] = (e != 0u) ? w : 513;
        }
    }

    short* seg0 = g_segmap + (size_t)(b * SEG + s0) * NST;
    #pragma unroll
    for (int j = 0; j < 8; j++)
        seg0[j * NST + tid] = (short)slot_state(idx[j]);
    seg0[un8 * NST + p4] = (short)slot_state(idx[8]);    // redundant, same value
}

// ---------------------------------------------------------------------------
// K_FIN: stitch + replay + scatter. One block per batch. uint4 global loads.
// Gathers straight from the 514-word table (32-lane random gather: ~3-way
// conflicts, far cheaper than the 16K-word replication fill it replaces).
// ---------------------------------------------------------------------------
#define SMAP_U4 ((SEG * NST * 2) / 16)   // 1032

__global__ void __launch_bounds__(256) k_fin(float* __restrict__ out) {
    __shared__ unsigned tabS[514];
    __shared__ __align__(16) int   sx[L];
    __shared__ __align__(16) short smap[SEG * NST];
    __shared__ short entry[SEG];
    int b = blockIdx.x;
    int tid = threadIdx.x;

    for (int i = tid; i < 514; i += 256) tabS[i] = g_tab[slot_src(i)];
    ((uint4*)sx)[tid] = ((const uint4*)(g_xidx + b * L))[tid];
    {
        const uint4* src = (const uint4*)(g_segmap + (size_t)b * SEG * NST);
        uint4* dst = (uint4*)smap;
        #pragma unroll
        for (int k = 0; k < 4; k++) dst[tid + 256 * k] = src[tid + 256 * k];
        if (tid < SMAP_U4 - 1024) dst[1024 + tid] = src[1024 + tid];
    }
    __syncthreads();

    if (tid == 0) {
        int st = V;   // ZERO
        #pragma unroll
        for (int s = 0; s < SEG; s++) { entry[s] = (short)st; st = smap[s * NST + st]; }
    }
    __syncthreads();

    if (tid < SEG) {
        int s   = tid;
        int ent = entry[s];
        int idx = (ent == V) ? 513 : ent;
        float* orow = out + (size_t)(b * L + s * SEGLEN) * V;
        #pragma unroll 8
        for (int t = 0; t < SEGLEN; t++) {
            unsigned e = tabS[idx];
            unsigned z = (unsigned)sx[s * SEGLEN + t] * (e & 0xFFFFu) + (e >> 16);
            int w = (int)(z & 255u) - (int)(z >> 8) + V;
            bool ok = (e != 0u);
            idx = ok ? w : 513;
            if (ok) {
                int oi = (w >= V) ? w - V : w;
                orow[(size_t)t * V + oi] = 1.0f;
            }
        }
    }
}

// ---------------------------------------------------------------------------
extern "C" void kernel_launch(void* const* d_in, const int* in_sizes, int n_in,
                              void* d_out, int out_size) {
    const float* x   = (const float*)d_in[0];   // [B, L, V] f32
    const float* W   = (const float*)d_in[1];   // [V, 2V]   f32
    const float* bb  = (const float*)d_in[2];   // [2V]      f32
    const int*   inv = (const int*)  d_in[3];   // [V]       i32

    const int dynsmem = 514 * REP * 4;          // 65792 B
    cudaFuncSetAttribute(k_B, cudaFuncAttributeMaxDynamicSharedMemorySize, dynsmem);

    k_A<<<TBLK + 2 * MIXB, 256>>>(W, bb, inv, (const uint4*)x, (uint4*)d_out);
    k_B<<<SEGBLK, 256, dynsmem>>>();
    k_fin<<<B, 256>>>((float*)d_out);
}